// round 4
// baseline (speedup 1.0000x reference)
#include <cuda_runtime.h>

#define BB 8
#define NN 512
#define PP 32
#define LL 3
#define KS 8           // n-splits for zpart (n-chunk = 64)

typedef unsigned long long ull;

// Scratch (device globals: no allocation in kernel_launch)
__device__ float g_t31[LL][BB*NN*PP];      // [l][b][n][p]
__device__ float g_nu[BB*PP*NN];           // t2[l+1] @ mu_l   [b][p][n]
__device__ float g_z[KS][BB*PP*NN];        // k-split partials of nu@adj

// ---- packed f32x2 helpers (sm_100+) ---------------------------------------
__device__ __forceinline__ ull pk(float lo, float hi) {
    ull r; asm("mov.b64 %0,{%1,%2};" : "=l"(r) : "f"(lo), "f"(hi)); return r;
}
__device__ __forceinline__ void upk(ull v, float& lo, float& hi) {
    asm("mov.b64 {%0,%1},%2;" : "=f"(lo), "=f"(hi) : "l"(v));
}
__device__ __forceinline__ ull fma2(ull a, ull b, ull c) {
    ull d; asm("fma.rn.f32x2 %0,%1,%2,%3;" : "=l"(d) : "l"(a), "l"(b), "l"(c));
    return d;
}
__device__ __forceinline__ ull add2(ull a, ull b) {
    ull d; asm("add.rn.f32x2 %0,%1,%2;" : "=l"(d) : "l"(a), "l"(b));
    return d;
}

union F4U2 { float4 f4; ull u2[2]; };

// ---- cp.async helpers ------------------------------------------------------
__device__ __forceinline__ void cp16(unsigned smem_dst, const void* gsrc) {
    asm volatile("cp.async.ca.shared.global [%0], [%1], 16;"
                 :: "r"(smem_dst), "l"(gsrc));
}
__device__ __forceinline__ void cp_commit() {
    asm volatile("cp.async.commit_group;");
}
template <int N>
__device__ __forceinline__ void cp_wait() {
    asm volatile("cp.async.wait_group %0;" :: "n"(N));
}

// ---------------------------------------------------------------------------
// K1 (fused over layers):
//   t31[l][b][n][p] = sum_m relu(v),  v = A + B*w[b,n,m] + C*s[b,m]
//   relu-sum via 0.5*(Sum v + Sum |v|), all accumulation packed f32x2.
// grid (N, B), block 256. lane = p; 8 warps split m; 3 layers interleaved.
// ---------------------------------------------------------------------------
__global__ __launch_bounds__(256) void edge_kernel(
    const float* __restrict__ x, const float* __restrict__ wgt,
    const float* __restrict__ t4)
{
    __shared__ float w_s[NN];
    __shared__ float s_s[NN];
    __shared__ float red_s[LL][8][PP];

    int n = blockIdx.x, b = blockIdx.y;
    int tid = threadIdx.x;
    int lane = tid & 31;
    int wid  = tid >> 5;

    const float* wrow = wgt + ((size_t)(b * NN + n)) * NN;
    const float* xb   = x + b * NN;

    for (int m = tid; m < NN; m += 256) {
        w_s[m] = wrow[m];
        s_s[m] = 2.0f * xb[m] - 1.0f;
    }

    float xn = xb[n];
    float sn = 2.0f * xn - 1.0f;

    ull A2[LL], B2[LL], C2[LL];
    #pragma unroll
    for (int l = 0; l < LL; l++) {
        const float* t4p = t4 + (l * PP + lane) * 4;
        float c0 = t4p[0], c1 = t4p[1], c2 = t4p[2], c3 = t4p[3];
        float A  = fmaf(c0, xn, fmaf(0.5f, c2, c3));
        float C  = -0.5f * c2 * sn;
        A2[l] = pk(A, A);
        B2[l] = pk(c1, c1);
        C2[l] = pk(C, C);
    }

    __syncthreads();

    const ull ABSM = 0x7fffffff7fffffffULL;
    ull sv[LL] = {0, 0, 0};   // packed sum of v   (0.0f bits are 0)
    ull sa[LL] = {0, 0, 0};   // packed sum of |v|

    int m0 = wid * (NN / 8);
    #pragma unroll 4
    for (int m = m0; m < m0 + NN / 8; m += 4) {
        F4U2 w4, s4;
        w4.f4 = *(const float4*)(w_s + m);
        s4.f4 = *(const float4*)(s_s + m);
        #pragma unroll
        for (int l = 0; l < LL; l++) {
            ull v0 = fma2(C2[l], s4.u2[0], fma2(B2[l], w4.u2[0], A2[l]));
            ull v1 = fma2(C2[l], s4.u2[1], fma2(B2[l], w4.u2[1], A2[l]));
            sv[l] = add2(sv[l], add2(v0, v1));
            sa[l] = add2(sa[l], add2(v0 & ABSM, v1 & ABSM));
        }
    }

    #pragma unroll
    for (int l = 0; l < LL; l++) {
        float a, bb, c, d;
        upk(sv[l], a, bb);
        upk(sa[l], c, d);
        red_s[l][wid][lane] = (a + bb) + (c + d);
    }
    __syncthreads();

    if (wid < LL) {
        float s = red_s[wid][0][lane];
        #pragma unroll
        for (int k = 1; k < 8; k++) s += red_s[wid][k][lane];
        g_t31[wid][(b * NN + n) * PP + lane] = 0.5f * s;
    }
}

// ---------------------------------------------------------------------------
// K2: z[ks][b][q][j] = sum_{n in 64-chunk ks} nu[b][q][n] * adj[b][n][j]
// grid (4, B, KS), block 256. cp.async double-buffered adj tiles.
// ---------------------------------------------------------------------------
__global__ __launch_bounds__(256) void zpart_kernel(const float* __restrict__ adj)
{
    __shared__ float a_s[2][16][128];
    __shared__ float mu_s[64][PP];    // [nn][q]

    int jt = blockIdx.x, b = blockIdx.y, ks = blockIdx.z;
    int tid  = threadIdx.x;
    int lane = tid & 31;
    int wid  = tid >> 5;
    int n0   = ks * 64;
    int j0   = jt * 128;

    // stage nu[b][q][n0..n0+64) transposed -> mu_s[nn][q]
    #pragma unroll
    for (int pass = 0; pass < 2; pass++) {
        int i   = tid + pass * 256;     // 0..511
        int qq  = i >> 4;               // 0..31
        int nn4 = (i & 15) * 4;         // 0..60
        float4 v = *(const float4*)(g_nu + (b * PP + qq) * NN + n0 + nn4);
        mu_s[nn4 + 0][qq] = v.x;
        mu_s[nn4 + 1][qq] = v.y;
        mu_s[nn4 + 2][qq] = v.z;
        mu_s[nn4 + 3][qq] = v.w;
    }

    auto stage = [&](int t, int buf) {
        #pragma unroll
        for (int pass = 0; pass < 2; pass++) {
            int i    = tid + pass * 256;
            int row  = i >> 5;
            int col4 = (i & 31) * 4;
            const float* src =
                adj + ((size_t)(b * NN + n0 + t * 16 + row)) * NN + j0 + col4;
            unsigned dst = (unsigned)__cvta_generic_to_shared(&a_s[buf][row][col4]);
            cp16(dst, src);
        }
        cp_commit();
    };

    stage(0, 0);

    float4 acc[4];
    #pragma unroll
    for (int i = 0; i < 4; i++) acc[i] = make_float4(0.f, 0.f, 0.f, 0.f);

    #pragma unroll
    for (int t = 0; t < 4; t++) {
        if (t + 1 < 4) { stage(t + 1, (t + 1) & 1); cp_wait<1>(); }
        else            cp_wait<0>();
        __syncthreads();

        int buf = t & 1;
        #pragma unroll
        for (int nn = 0; nn < 16; nn++) {
            float4 a4 = *(const float4*)&a_s[buf][nn][lane * 4];
            float4 m4 = *(const float4*)&mu_s[t * 16 + nn][wid * 4];
            acc[0].x = fmaf(m4.x, a4.x, acc[0].x);
            acc[0].y = fmaf(m4.x, a4.y, acc[0].y);
            acc[0].z = fmaf(m4.x, a4.z, acc[0].z);
            acc[0].w = fmaf(m4.x, a4.w, acc[0].w);
            acc[1].x = fmaf(m4.y, a4.x, acc[1].x);
            acc[1].y = fmaf(m4.y, a4.y, acc[1].y);
            acc[1].z = fmaf(m4.y, a4.z, acc[1].z);
            acc[1].w = fmaf(m4.y, a4.w, acc[1].w);
            acc[2].x = fmaf(m4.z, a4.x, acc[2].x);
            acc[2].y = fmaf(m4.z, a4.y, acc[2].y);
            acc[2].z = fmaf(m4.z, a4.z, acc[2].z);
            acc[2].w = fmaf(m4.z, a4.w, acc[2].w);
            acc[3].x = fmaf(m4.w, a4.x, acc[3].x);
            acc[3].y = fmaf(m4.w, a4.y, acc[3].y);
            acc[3].z = fmaf(m4.w, a4.z, acc[3].z);
            acc[3].w = fmaf(m4.w, a4.w, acc[3].w);
        }
        __syncthreads();
    }

    float* gz = g_z[ks] + ((size_t)(b * PP + wid * 4)) * NN + j0 + lane * 4;
    #pragma unroll
    for (int i = 0; i < 4; i++)
        *(float4*)(gz + (size_t)i * NN) = acc[i];
}

// ---------------------------------------------------------------------------
// K3: mu[b,p,j] = relu( term1 + sum_ks z[ks] + sum_q t3[p,q]*t31[q,j] )
//     layer<2:  g_nu[b,p,j] = sum_q t2[l+1][p,q]*mu[q,j]
//     layer==2: out = mu
// grid (N/8, B), block 256: p = tid>>3 (32), jj = tid&7 (8 j per block).
// ---------------------------------------------------------------------------
__global__ __launch_bounds__(256) void epilogue_kernel(
    const float* __restrict__ x, const float* __restrict__ extra,
    const float* __restrict__ t1, const float* __restrict__ t2,
    const float* __restrict__ t3, int layer, int has_z,
    float* __restrict__ out)
{
    __shared__ float t3_s[PP][33];    // [q][p]
    __shared__ float t2n_s[PP][33];   // [q][p] of t2[layer+1]
    __shared__ float t31_s[PP][9];    // [q][jj]
    __shared__ float mu_s[PP][9];     // [q][jj]

    int b = blockIdx.y;
    int tid = threadIdx.x;
    int p  = tid >> 3;
    int jj = tid & 7;
    int j  = blockIdx.x * 8 + jj;

    int lnext = (layer < 2) ? layer + 1 : layer;
    #pragma unroll
    for (int pass = 0; pass < 4; pass++) {
        int idx = tid + pass * 256;      // 0..1023
        int pr = idx >> 5, qc = idx & 31;
        t3_s[qc][pr]  = t3[layer * PP * PP + idx];
        t2n_s[qc][pr] = t2[lnext * PP * PP + idx];
    }
    {
        int q = tid & 31, j2 = tid >> 5;
        t31_s[q][j2] = g_t31[layer][((size_t)b * NN + blockIdx.x * 8 + j2) * PP + q];
    }
    __syncthreads();

    float xv = x[b * NN + j];
    float ev = extra[b * NN + j];
    const float* t1p = t1 + (layer * PP + p) * 3;
    float acc = fmaf(t1p[0], 1.0f - xv, fmaf(t1p[2], ev, t1p[1]));

    if (has_z) {
        size_t base = (size_t)(b * PP + p) * NN + j;
        float zs = 0.0f;
        #pragma unroll
        for (int ks = 0; ks < KS; ks++) zs += g_z[ks][base];
        acc += zs;
    }

    float t3acc = 0.0f;
    #pragma unroll
    for (int q = 0; q < PP; q++)
        t3acc = fmaf(t3_s[q][p], t31_s[q][jj], t3acc);

    float mu = fmaxf(acc + t3acc, 0.0f);

    if (layer == 2) {
        out[(size_t)(b * PP + p) * NN + j] = mu;
        return;
    }

    mu_s[p][jj] = mu;
    __syncthreads();

    float nu = 0.0f;
    #pragma unroll
    for (int q = 0; q < PP; q++)
        nu = fmaf(t2n_s[q][p], mu_s[q][jj], nu);

    g_nu[(size_t)(b * PP + p) * NN + j] = nu;
}

// ---------------------------------------------------------------------------
extern "C" void kernel_launch(void* const* d_in, const int* in_sizes, int n_in,
                              void* d_out, int out_size)
{
    const float* x     = (const float*)d_in[0];
    const float* adj   = (const float*)d_in[1];
    const float* wgt   = (const float*)d_in[2];
    const float* extra = (const float*)d_in[3];
    const float* t1    = (const float*)d_in[4];
    const float* t2    = (const float*)d_in[5];
    const float* t3    = (const float*)d_in[6];
    const float* t4    = (const float*)d_in[7];
    float* out = (float*)d_out;

    dim3 edge_grid(NN, BB);
    dim3 z_grid(4, BB, KS);
    dim3 epi_grid(NN / 8, BB);

    // all 3 layers' t31 in one fused launch
    edge_kernel<<<edge_grid, 256>>>(x, wgt, t4);

    // layer 0: mu_prev = 0 -> no z. epi writes g_nu = t2[1] @ mu0
    epilogue_kernel<<<epi_grid, 256>>>(x, extra, t1, t2, t3, 0, 0, out);

    // layer 1: z = nu @ adj ; epi writes g_nu = t2[2] @ mu1
    zpart_kernel<<<z_grid, 256>>>(adj);
    epilogue_kernel<<<epi_grid, 256>>>(x, extra, t1, t2, t3, 1, 1, out);

    // layer 2: z = nu @ adj ; epi writes mu2 -> d_out
    zpart_kernel<<<z_grid, 256>>>(adj);
    epilogue_kernel<<<epi_grid, 256>>>(x, extra, t1, t2, t3, 2, 1, out);
}

// round 5
// speedup vs baseline: 1.1200x; 1.1200x over previous
#include <cuda_runtime.h>

#define BB 8
#define NN 512
#define PP 32
#define LL 3

typedef unsigned long long ull;

// Scratch (device globals: no allocation in kernel_launch)
__device__ float g_t31[LL][BB*NN*PP];      // [l][b][n][p]
__device__ float g_nu[BB*PP*NN];           // t2[l+1] @ mu_l   [b][p][n]

// ---- packed f32x2 helpers (sm_100+) ---------------------------------------
__device__ __forceinline__ ull pk(float lo, float hi) {
    ull r; asm("mov.b64 %0,{%1,%2};" : "=l"(r) : "f"(lo), "f"(hi)); return r;
}
__device__ __forceinline__ void upk(ull v, float& lo, float& hi) {
    asm("mov.b64 {%0,%1},%2;" : "=f"(lo), "=f"(hi) : "l"(v));
}
__device__ __forceinline__ ull fma2(ull a, ull b, ull c) {
    ull d; asm("fma.rn.f32x2 %0,%1,%2,%3;" : "=l"(d) : "l"(a), "l"(b), "l"(c));
    return d;
}
__device__ __forceinline__ ull add2(ull a, ull b) {
    ull d; asm("add.rn.f32x2 %0,%1,%2;" : "=l"(d) : "l"(a), "l"(b));
    return d;
}

union F4U2 { float4 f4; ull u2[2]; };

// ---- cp.async helpers ------------------------------------------------------
__device__ __forceinline__ void cp16(void* smem_dst, const void* gsrc) {
    unsigned d = (unsigned)__cvta_generic_to_shared(smem_dst);
    asm volatile("cp.async.ca.shared.global [%0], [%1], 16;"
                 :: "r"(d), "l"(gsrc));
}
__device__ __forceinline__ void cp_commit() {
    asm volatile("cp.async.commit_group;");
}
template <int N>
__device__ __forceinline__ void cp_wait() {
    asm volatile("cp.async.wait_group %0;" :: "n"(N));
}

// ---------------------------------------------------------------------------
// K1 (fused over layers):
//   t31[l][b][n][p] = sum_m relu(v),  v = A + B*w[b,n,m] + C*s[b,m]
//   = 0.5*( Sum v  +  Sum |v| )
//   Sum v = 512*A + B*Sum(w) + C*Sum(s)   <- closed form, row sums
//   main loop accumulates only Sum|v| (packed f32x2 + 64-bit AND abs)
// grid (N, B), block 256. lane = p; 8 warps split m; 3 layers interleaved.
// ---------------------------------------------------------------------------
__global__ __launch_bounds__(256) void edge_kernel(
    const float* __restrict__ x, const float* __restrict__ wgt,
    const float* __restrict__ t4)
{
    __shared__ float w_s[NN];
    __shared__ float s_s[NN];
    __shared__ float red_s[LL][8][PP];
    __shared__ float rw_s[8], rs_s[8];

    int n = blockIdx.x, b = blockIdx.y;
    int tid = threadIdx.x;
    int lane = tid & 31;
    int wid  = tid >> 5;

    const float* wrow = wgt + ((size_t)(b * NN + n)) * NN;
    const float* xb   = x + b * NN;

    float pw = 0.f, ps = 0.f;
    for (int m = tid; m < NN; m += 256) {
        float w = wrow[m];
        float s = 2.0f * xb[m] - 1.0f;
        w_s[m] = w;
        s_s[m] = s;
        pw += w;
        ps += s;
    }
    #pragma unroll
    for (int o = 16; o; o >>= 1) {
        pw += __shfl_xor_sync(0xffffffffu, pw, o);
        ps += __shfl_xor_sync(0xffffffffu, ps, o);
    }
    if (lane == 0) { rw_s[wid] = pw; rs_s[wid] = ps; }

    float xn = xb[n];
    float sn = 2.0f * xn - 1.0f;

    float As[LL], Bs[LL], Cs[LL];
    ull A2[LL], B2[LL], C2[LL];
    #pragma unroll
    for (int l = 0; l < LL; l++) {
        const float* t4p = t4 + (l * PP + lane) * 4;
        float c0 = t4p[0], c1 = t4p[1], c2 = t4p[2], c3 = t4p[3];
        float A  = fmaf(c0, xn, fmaf(0.5f, c2, c3));
        float C  = -0.5f * c2 * sn;
        As[l] = A; Bs[l] = c1; Cs[l] = C;
        A2[l] = pk(A, A);
        B2[l] = pk(c1, c1);
        C2[l] = pk(C, C);
    }

    __syncthreads();

    float sw = 0.f, ss = 0.f;
    #pragma unroll
    for (int k = 0; k < 8; k++) { sw += rw_s[k]; ss += rs_s[k]; }

    const ull ABSM = 0x7fffffff7fffffffULL;
    ull sa[LL] = {0, 0, 0};   // packed sum of |v|

    int m0 = wid * (NN / 8);
    #pragma unroll 4
    for (int m = m0; m < m0 + NN / 8; m += 4) {
        F4U2 w4, s4;
        w4.f4 = *(const float4*)(w_s + m);
        s4.f4 = *(const float4*)(s_s + m);
        #pragma unroll
        for (int l = 0; l < LL; l++) {
            ull v0 = fma2(C2[l], s4.u2[0], fma2(B2[l], w4.u2[0], A2[l]));
            ull v1 = fma2(C2[l], s4.u2[1], fma2(B2[l], w4.u2[1], A2[l]));
            sa[l] = add2(sa[l], add2(v0 & ABSM, v1 & ABSM));
        }
    }

    #pragma unroll
    for (int l = 0; l < LL; l++) {
        float a, bb;
        upk(sa[l], a, bb);
        red_s[l][wid][lane] = a + bb;
    }
    __syncthreads();

    if (wid < LL) {
        int l = wid;
        float stot = red_s[l][0][lane];
        #pragma unroll
        for (int k = 1; k < 8; k++) stot += red_s[l][k][lane];
        float sv = fmaf(512.0f, As[l], fmaf(Bs[l], sw, Cs[l] * ss));
        g_t31[l][(b * NN + n) * PP + lane] = 0.5f * (sv + stot);
    }
}

// ---------------------------------------------------------------------------
// K2 (per layer, fused z + epilogue):
//   z[q][j] = sum_n nu[b][q][n] * adj[b][n][j]           (registers, full n)
//   mu[p][j] = relu( term1 + z[p][j] + sum_q t3[p,q]*t31[q,j] )
//   layer<2:  g_nu = t2[l+1] @ mu ;  layer==2: out = mu
// grid (16, B), block 256. warp w owns q/p = 4w..4w+3; lane owns j.
// ---------------------------------------------------------------------------
__global__ __launch_bounds__(256) void layer_kernel(
    const float* __restrict__ x, const float* __restrict__ extra,
    const float* __restrict__ adj,
    const float* __restrict__ t1, const float* __restrict__ t2,
    const float* __restrict__ t3, int layer, int has_z,
    float* __restrict__ out)
{
    __shared__ float a_s[2][32][32];    // [n][j] adj tile
    __shared__ float nu_s[2][32][32];   // [q][n] nu tile
    __shared__ float t3_s[PP][33];      // [q][p]
    __shared__ float t2n_s[PP][33];     // [q][p] of t2[layer+1]
    __shared__ float t31_s[PP][33];     // [q][j]
    __shared__ float mu_s[PP][33];      // [p][j]

    int jt = blockIdx.x, b = blockIdx.y;
    int tid = threadIdx.x;
    int lane = tid & 31;
    int w = tid >> 5;
    int j0 = jt * 32;
    int j = j0 + lane;

    int lnext = (layer < 2) ? layer + 1 : layer;
    #pragma unroll
    for (int pass = 0; pass < 4; pass++) {
        int idx = tid + pass * 256;          // p*32+q
        int p = idx >> 5, q = idx & 31;
        t3_s[q][p]  = t3[layer * PP * PP + idx];
        t2n_s[q][p] = t2[lnext * PP * PP + idx];
    }
    #pragma unroll
    for (int pass = 0; pass < 4; pass++) {
        int idx = tid + pass * 256;
        int jj = idx >> 5, q = idx & 31;
        t31_s[q][jj] = g_t31[layer][((size_t)b * NN + j0 + jj) * PP + q];
    }

    float acc0 = 0.f, acc1 = 0.f, acc2 = 0.f, acc3 = 0.f;

    if (has_z) {
        int srow = tid >> 3;             // 0..31
        int scol = (tid & 7) * 4;        // 0..28

        const float* abase = adj + ((size_t)(b * NN + srow)) * NN + j0 + scol;
        const float* nbase = g_nu + ((size_t)(b * PP + srow)) * NN + scol;

        // stage tile t (rows n = 32t..32t+31)
        auto stage = [&](int t, int buf) {
            cp16(&a_s[buf][srow][scol], abase + (size_t)t * 32 * NN);
            cp16(&nu_s[buf][srow][scol], nbase + t * 32);
            cp_commit();
        };

        stage(0, 0);
        __syncthreads();   // also covers t3_s/t31_s staging

        #pragma unroll 1
        for (int t = 0; t < 16; t++) {
            if (t < 15) { stage(t + 1, (t + 1) & 1); cp_wait<1>(); }
            else          cp_wait<0>();
            __syncthreads();

            int buf = t & 1;
            #pragma unroll
            for (int nn = 0; nn < 32; nn += 4) {
                float4 nv0 = *(const float4*)&nu_s[buf][w * 4 + 0][nn];
                float4 nv1 = *(const float4*)&nu_s[buf][w * 4 + 1][nn];
                float4 nv2 = *(const float4*)&nu_s[buf][w * 4 + 2][nn];
                float4 nv3 = *(const float4*)&nu_s[buf][w * 4 + 3][nn];
                float a0 = a_s[buf][nn + 0][lane];
                float a1 = a_s[buf][nn + 1][lane];
                float a2 = a_s[buf][nn + 2][lane];
                float a3 = a_s[buf][nn + 3][lane];
                acc0 = fmaf(nv0.x, a0, acc0); acc0 = fmaf(nv0.y, a1, acc0);
                acc0 = fmaf(nv0.z, a2, acc0); acc0 = fmaf(nv0.w, a3, acc0);
                acc1 = fmaf(nv1.x, a0, acc1); acc1 = fmaf(nv1.y, a1, acc1);
                acc1 = fmaf(nv1.z, a2, acc1); acc1 = fmaf(nv1.w, a3, acc1);
                acc2 = fmaf(nv2.x, a0, acc2); acc2 = fmaf(nv2.y, a1, acc2);
                acc2 = fmaf(nv2.z, a2, acc2); acc2 = fmaf(nv2.w, a3, acc2);
                acc3 = fmaf(nv3.x, a0, acc3); acc3 = fmaf(nv3.y, a1, acc3);
                acc3 = fmaf(nv3.z, a2, acc3); acc3 = fmaf(nv3.w, a3, acc3);
            }
            __syncthreads();
        }
    } else {
        __syncthreads();
    }

    // epilogue: thread (w, lane) handles p = 4w..4w+3, j = lane
    float xv = x[b * NN + j];
    float ev = extra[b * NN + j];
    float zacc[4] = {acc0, acc1, acc2, acc3};
    float mu[4];

    #pragma unroll
    for (int i = 0; i < 4; i++) {
        int p = w * 4 + i;
        const float* t1p = t1 + (layer * PP + p) * 3;
        float o = fmaf(t1p[0], 1.0f - xv, fmaf(t1p[2], ev, t1p[1])) + zacc[i];
        float t3a = 0.0f;
        #pragma unroll
        for (int q = 0; q < PP; q++)
            t3a = fmaf(t3_s[q][p], t31_s[q][lane], t3a);
        mu[i] = fmaxf(o + t3a, 0.0f);
    }

    if (layer == 2) {
        #pragma unroll
        for (int i = 0; i < 4; i++)
            out[((size_t)b * PP + w * 4 + i) * NN + j] = mu[i];
        return;
    }

    #pragma unroll
    for (int i = 0; i < 4; i++)
        mu_s[w * 4 + i][lane] = mu[i];
    __syncthreads();

    #pragma unroll
    for (int i = 0; i < 4; i++) {
        int p = w * 4 + i;
        float nu = 0.0f;
        #pragma unroll
        for (int q = 0; q < PP; q++)
            nu = fmaf(t2n_s[q][p], mu_s[q][lane], nu);
        g_nu[((size_t)b * PP + p) * NN + j] = nu;
    }
}

// ---------------------------------------------------------------------------
extern "C" void kernel_launch(void* const* d_in, const int* in_sizes, int n_in,
                              void* d_out, int out_size)
{
    const float* x     = (const float*)d_in[0];
    const float* adj   = (const float*)d_in[1];
    const float* wgt   = (const float*)d_in[2];
    const float* extra = (const float*)d_in[3];
    const float* t1    = (const float*)d_in[4];
    const float* t2    = (const float*)d_in[5];
    const float* t3    = (const float*)d_in[6];
    const float* t4    = (const float*)d_in[7];
    float* out = (float*)d_out;

    dim3 edge_grid(NN, BB);
    dim3 layer_grid(NN / 32, BB);

    // all 3 layers' t31 in one fused launch
    edge_kernel<<<edge_grid, 256>>>(x, wgt, t4);

    // layer 0: no z; writes g_nu = t2[1] @ mu0
    layer_kernel<<<layer_grid, 256>>>(x, extra, adj, t1, t2, t3, 0, 0, out);
    // layer 1: z = nu @ adj; writes g_nu = t2[2] @ mu1
    layer_kernel<<<layer_grid, 256>>>(x, extra, adj, t1, t2, t3, 1, 1, out);
    // layer 2: z = nu @ adj; writes mu2 -> d_out
    layer_kernel<<<layer_grid, 256>>>(x, extra, adj, t1, t2, t3, 2, 1, out);
}